// round 13
// baseline (speedup 1.0000x reference)
#include <cuda_runtime.h>
#include <cuda_fp16.h>

// 3D trilinear grid_sample, align_corners=False, padding_mode='border'
// image: [B, C, D, H, W] float32   (B=2, C=2, D=H=W=128)
// flow:  [B, 3, D, H, W] float32
// out:   [B, C, D, H, W] float32
//
// Scratch: fp16 y-duplicated records, 8B/voxel:
//   rec[p] = { h2(c0,c1)@(y,x), h2(c0,c1)@(y+1,x) }   (y+1 clamped)
// stored at TWO alignments:
//   A4[j] = { rec[2j],   rec[2j+1] }   (even-x0 pairs, 16B aligned)
//   B [j] = { rec[2j+1], rec[2j+2] }   (odd-x0 pairs,  16B aligned)
// Gather: per voxel TWO LDG.128 (z0-face, z1-face); each carries the full
// (y0/y1) x (x0/x1) x (c0/c1) footprint of that face. x0==W-1 reads a
// neighbor/pad hi-half that carries exact weight tx==0.

#define B_ 2
#define C_ 2
#define D_ 128
#define H_ 128
#define W_ 128
#define N_ (D_ * H_ * W_)

__device__ uint4 g_pa[B_][N_ / 2];        // A4: even-aligned pairs
__device__ uint4 g_pb[B_][N_ / 2 + 4];    // B: shifted pairs (+pad, zero-init)

__device__ __forceinline__ unsigned h2u(__half2 h)
{
    return *reinterpret_cast<unsigned*>(&h);
}

__global__ __launch_bounds__(256) void interleave_kernel(
    const float* __restrict__ image)
{
    // each thread builds 4 consecutive-x records of one (b,z,y) row
    int t = blockIdx.x * blockDim.x + threadIdx.x;   // 0 .. B*N/4-1
    int x  = (t & 31) * 4;                           // 0,4,...,124
    int y  = (t >> 5) & (H_ - 1);
    int z  = (t >> 12) & (D_ - 1);
    int b  = t >> 19;

    const float* img0 = image + ((size_t)b * C_ + 0) * N_;
    const float* img1 = image + ((size_t)b * C_ + 1) * N_;

    int row0 = (z * H_ + y) * W_;
    int row1 = (z * H_ + min(y + 1, H_ - 1)) * W_;

    float4 c0a = __ldcs(reinterpret_cast<const float4*>(img0 + row0 + x));
    float4 c1a = __ldcs(reinterpret_cast<const float4*>(img1 + row0 + x));
    float4 c0b = __ldcs(reinterpret_cast<const float4*>(img0 + row1 + x));
    float4 c1b = __ldcs(reinterpret_cast<const float4*>(img1 + row1 + x));

    // x+4 elements (clamped at row end; only ever consumed with weight 0)
    float c0an, c1an, c0bn, c1bn;
    if (x == W_ - 4) {
        c0an = c0a.w; c1an = c1a.w; c0bn = c0b.w; c1bn = c1b.w;
    } else {
        c0an = __ldcs(img0 + row0 + x + 4);
        c1an = __ldcs(img1 + row0 + x + 4);
        c0bn = __ldcs(img0 + row1 + x + 4);
        c1bn = __ldcs(img1 + row1 + x + 4);
    }

    // ay[i] = h2(c0,c1) at (y,   x+i);  by[i] = h2(c0,c1) at (y+1, x+i)
    unsigned ay0 = h2u(__floats2half2_rn(c0a.x, c1a.x));
    unsigned ay1 = h2u(__floats2half2_rn(c0a.y, c1a.y));
    unsigned ay2 = h2u(__floats2half2_rn(c0a.z, c1a.z));
    unsigned ay3 = h2u(__floats2half2_rn(c0a.w, c1a.w));
    unsigned ay4 = h2u(__floats2half2_rn(c0an,  c1an));
    unsigned by0 = h2u(__floats2half2_rn(c0b.x, c1b.x));
    unsigned by1 = h2u(__floats2half2_rn(c0b.y, c1b.y));
    unsigned by2 = h2u(__floats2half2_rn(c0b.z, c1b.z));
    unsigned by3 = h2u(__floats2half2_rn(c0b.w, c1b.w));
    unsigned by4 = h2u(__floats2half2_rn(c0bn,  c1bn));

    int j = (row0 + x) >> 1;                         // pair index (even)
    uint4* dA = &g_pa[b][j];
    dA[0] = make_uint4(ay0, by0, ay1, by1);          // {rec x, rec x+1}
    dA[1] = make_uint4(ay2, by2, ay3, by3);          // {rec x+2, rec x+3}
    uint4* dB = &g_pb[b][j];
    dB[0] = make_uint4(ay1, by1, ay2, by2);          // {rec x+1, rec x+2}
    dB[1] = make_uint4(ay3, by3, ay4, by4);          // {rec x+3, rec x+4}
}

struct Coord {
    int j0, j1;          // 16B-pair indices for the z0/z1 faces
    int sel;             // x0 parity: 0 -> A4, 1 -> B
    float tx, ty, tz;
};

__device__ __forceinline__ Coord setup(int x, int y, int z,
                                       float fx, float fy, float fz)
{
    constexpr float sW = (float)W_ / (float)(W_ - 1);
    constexpr float sH = (float)H_ / (float)(H_ - 1);
    constexpr float sD = (float)D_ / (float)(D_ - 1);

    float ix = fminf(fmaxf(fmaf((float)x + fx, sW, -0.5f), 0.0f), (float)(W_ - 1));
    float iy = fminf(fmaxf(fmaf((float)y + fy, sH, -0.5f), 0.0f), (float)(H_ - 1));
    float iz = fminf(fmaxf(fmaf((float)z + fz, sD, -0.5f), 0.0f), (float)(D_ - 1));

    float x0f = floorf(ix), y0f = floorf(iy), z0f = floorf(iz);

    Coord c;
    c.tx = ix - x0f; c.ty = iy - y0f; c.tz = iz - z0f;
    int x0 = (int)x0f, y0 = (int)y0f, z0 = (int)z0f;
    int z1 = min(z0 + 1, D_ - 1);
    c.sel = x0 & 1;
    c.j0 = (((z0 * H_ + y0) * W_) + x0) >> 1;
    c.j1 = (((z1 * H_ + y0) * W_) + x0) >> 1;
    return c;
}

// one z-face: q = {y0@x0, y1@x0, y0@x1, y1@x1}, each h2(c0,c1). fp32 lerps.
__device__ __forceinline__ float2 face_lerp(uint4 q, float ty, float tx)
{
    float2 a0 = __half22float2(*reinterpret_cast<const __half2*>(&q.x));
    float2 a1 = __half22float2(*reinterpret_cast<const __half2*>(&q.y));
    float2 b0 = __half22float2(*reinterpret_cast<const __half2*>(&q.z));
    float2 b1 = __half22float2(*reinterpret_cast<const __half2*>(&q.w));

    // lerp y within each x column, then lerp x
    float lx = fmaf(ty, a1.x - a0.x, a0.x);
    float ly = fmaf(ty, a1.y - a0.y, a0.y);
    float rx = fmaf(ty, b1.x - b0.x, b0.x);
    float ry = fmaf(ty, b1.y - b0.y, b0.y);
    return make_float2(fmaf(tx, rx - lx, lx),
                       fmaf(tx, ry - ly, ly));
}

__global__ __launch_bounds__(256) void warp3d_kernel(
    const float* __restrict__ flow,
    float* __restrict__ out)
{
    int tid = blockIdx.x * blockDim.x + threadIdx.x;   // 0 .. B*N/2-1
    int b = tid >> 20;                                 // tid / (N_/2)
    int p = (tid & (N_ / 2 - 1)) * 2;                  // even voxel index

    int x = p & (W_ - 1);
    int y = (p >> 7) & (H_ - 1);
    int z = p >> 14;

    const float* fb = flow + (size_t)b * 3 * N_;
    float2 fx2 = __ldcs(reinterpret_cast<const float2*>(fb + p));
    float2 fy2 = __ldcs(reinterpret_cast<const float2*>(fb + N_ + p));
    float2 fz2 = __ldcs(reinterpret_cast<const float2*>(fb + 2 * N_ + p));

    Coord ca = setup(x,     y, z, fx2.x, fy2.x, fz2.x);
    Coord cb = setup(x + 1, y, z, fx2.y, fy2.y, fz2.y);

    const uint4* pA = g_pa[b];
    const uint4* pB = g_pb[b];
    const uint4* sa = ca.sel ? pB : pA;
    const uint4* sb = cb.sel ? pB : pA;

    // 4 gathers total (2 per voxel)
    uint4 qa0 = __ldg(sa + ca.j0);
    uint4 qa1 = __ldg(sa + ca.j1);
    uint4 qb0 = __ldg(sb + cb.j0);
    uint4 qb1 = __ldg(sb + cb.j1);

    float2 af0 = face_lerp(qa0, ca.ty, ca.tx);
    float2 af1 = face_lerp(qa1, ca.ty, ca.tx);
    float2 bf0 = face_lerp(qb0, cb.ty, cb.tx);
    float2 bf1 = face_lerp(qb1, cb.ty, cb.tx);

    float aoutx = fmaf(ca.tz, af1.x - af0.x, af0.x);
    float aouty = fmaf(ca.tz, af1.y - af0.y, af0.y);
    float boutx = fmaf(cb.tz, bf1.x - bf0.x, bf0.x);
    float bouty = fmaf(cb.tz, bf1.y - bf0.y, bf0.y);

    float* o0 = out + ((size_t)b * C_ + 0) * N_ + p;
    float* o1 = out + ((size_t)b * C_ + 1) * N_ + p;
    __stcs(reinterpret_cast<float2*>(o0), make_float2(aoutx, boutx));
    __stcs(reinterpret_cast<float2*>(o1), make_float2(aouty, bouty));
}

extern "C" void kernel_launch(void* const* d_in, const int* in_sizes, int n_in,
                              void* d_out, int out_size)
{
    const float* image = (const float*)d_in[0];
    const float* flow  = (const float*)d_in[1];
    float* out = (float*)d_out;

    {
        constexpr int total = B_ * N_ / 4;
        interleave_kernel<<<total / 256, 256>>>(image);
    }
    {
        constexpr int total = B_ * N_ / 2;
        warp3d_kernel<<<total / 256, 256>>>(flow, out);
    }
}

// round 14
// speedup vs baseline: 1.1627x; 1.1627x over previous
#include <cuda_runtime.h>
#include <cuda_fp16.h>

// 3D trilinear grid_sample, align_corners=False, padding_mode='border'
// image: [B, C, D, H, W] float32   (B=2, C=2, D=H=W=128)
// flow:  [B, 3, D, H, W] float32
// out:   [B, C, D, H, W] float32
//
// Scratch (33.5MB, L2-resident): fp16 y-duplicated records, 8B/voxel:
//   rec[p] = { h2(c0,c1)@(y,x), h2(c0,c1)@(y+1,x) }   (y+1 clamped)
// viewed as 16B pairs A[j] = {rec 2j, rec 2j+1}.
// Gather per z-face: one LDG.128 at j=idx>>1; when idx is odd, a predicated
// LDG.64 from A[j+1] supplies rec(idx+1). Values fetched past the x-border
// carry exact weight tx==0.

#define B_ 2
#define C_ 2
#define D_ 128
#define H_ 128
#define W_ 128
#define N_ (D_ * H_ * W_)

__device__ __align__(16) uint2 g_py[B_ * N_ + 8];   // +pad (zero-init)

__device__ __forceinline__ unsigned h2u(__half2 h)
{
    return *reinterpret_cast<unsigned*>(&h);
}

__global__ __launch_bounds__(256) void interleave_kernel(
    const float* __restrict__ image)
{
    // each thread builds 4 consecutive-x records of one (b,z,y) row
    int t = blockIdx.x * blockDim.x + threadIdx.x;   // 0 .. B*N/4-1
    int x  = (t & 31) * 4;                           // 0,4,...,124
    int y  = (t >> 5) & (H_ - 1);
    int z  = (t >> 12) & (D_ - 1);
    int b  = t >> 19;

    const float* img0 = image + ((size_t)b * C_ + 0) * N_;
    const float* img1 = image + ((size_t)b * C_ + 1) * N_;

    int row0 = (z * H_ + y) * W_;
    int row1 = (z * H_ + min(y + 1, H_ - 1)) * W_;

    float4 c0a = __ldcs(reinterpret_cast<const float4*>(img0 + row0 + x));
    float4 c1a = __ldcs(reinterpret_cast<const float4*>(img1 + row0 + x));
    float4 c0b = __ldcs(reinterpret_cast<const float4*>(img0 + row1 + x));
    float4 c1b = __ldcs(reinterpret_cast<const float4*>(img1 + row1 + x));

    uint2 r0 = make_uint2(h2u(__floats2half2_rn(c0a.x, c1a.x)),
                          h2u(__floats2half2_rn(c0b.x, c1b.x)));
    uint2 r1 = make_uint2(h2u(__floats2half2_rn(c0a.y, c1a.y)),
                          h2u(__floats2half2_rn(c0b.y, c1b.y)));
    uint2 r2 = make_uint2(h2u(__floats2half2_rn(c0a.z, c1a.z)),
                          h2u(__floats2half2_rn(c0b.z, c1b.z)));
    uint2 r3 = make_uint2(h2u(__floats2half2_rn(c0a.w, c1a.w)),
                          h2u(__floats2half2_rn(c0b.w, c1b.w)));

    uint4* dst = reinterpret_cast<uint4*>(&g_py[(size_t)b * N_ + row0 + x]);
    dst[0] = make_uint4(r0.x, r0.y, r1.x, r1.y);
    dst[1] = make_uint4(r2.x, r2.y, r3.x, r3.y);
}

struct Coord {
    int i0, i1;          // record indices of (z0,y0,x0) and (z1,y0,x0)
    float tx, ty, tz;
};

__device__ __forceinline__ Coord setup(int x, int y, int z,
                                       float fx, float fy, float fz)
{
    constexpr float sW = (float)W_ / (float)(W_ - 1);
    constexpr float sH = (float)H_ / (float)(H_ - 1);
    constexpr float sD = (float)D_ / (float)(D_ - 1);

    float ix = fminf(fmaxf(fmaf((float)x + fx, sW, -0.5f), 0.0f), (float)(W_ - 1));
    float iy = fminf(fmaxf(fmaf((float)y + fy, sH, -0.5f), 0.0f), (float)(H_ - 1));
    float iz = fminf(fmaxf(fmaf((float)z + fz, sD, -0.5f), 0.0f), (float)(D_ - 1));

    float x0f = floorf(ix), y0f = floorf(iy), z0f = floorf(iz);

    Coord c;
    c.tx = ix - x0f; c.ty = iy - y0f; c.tz = iz - z0f;
    int x0 = (int)x0f, y0 = (int)y0f, z0 = (int)z0f;
    int z1 = min(z0 + 1, D_ - 1);
    c.i0 = (z0 * H_ + y0) * W_ + x0;
    c.i1 = (z1 * H_ + y0) * W_ + x0;
    return c;
}

// fetch records idx, idx+1 from the pair-aligned view and bilerp the face.
// lo = rec(idx) = {y0@x0, y1@x0};  hi = rec(idx+1) = {y0@x1, y1@x1}
__device__ __forceinline__ float2 face_fetch_lerp(const uint2* __restrict__ base,
                                                  int idx, float ty, float tx)
{
    const uint4* A = reinterpret_cast<const uint4*>(base);
    int j = idx >> 1;
    bool odd = (idx & 1) != 0;

    uint4 q = __ldg(A + j);
    uint2 e = make_uint2(0u, 0u);
    if (odd) e = __ldg(reinterpret_cast<const uint2*>(A + j + 1));

    uint2 lo = odd ? make_uint2(q.z, q.w) : make_uint2(q.x, q.y);
    uint2 hi = odd ? e                    : make_uint2(q.z, q.w);

    float2 l0 = __half22float2(*reinterpret_cast<const __half2*>(&lo.x));
    float2 l1 = __half22float2(*reinterpret_cast<const __half2*>(&lo.y));
    float2 h0 = __half22float2(*reinterpret_cast<const __half2*>(&hi.x));
    float2 h1 = __half22float2(*reinterpret_cast<const __half2*>(&hi.y));

    // lerp y in each column, then lerp x
    float lx = fmaf(ty, l1.x - l0.x, l0.x);
    float ly = fmaf(ty, l1.y - l0.y, l0.y);
    float rx = fmaf(ty, h1.x - h0.x, h0.x);
    float ry = fmaf(ty, h1.y - h0.y, h0.y);
    return make_float2(fmaf(tx, rx - lx, lx),
                       fmaf(tx, ry - ly, ly));
}

__global__ __launch_bounds__(256, 6) void warp3d_kernel(
    const float* __restrict__ flow,
    float* __restrict__ out)
{
    int tid = blockIdx.x * blockDim.x + threadIdx.x;   // 0 .. B*N/2-1
    int b = tid >> 20;                                 // tid / (N_/2)
    int p = (tid & (N_ / 2 - 1)) * 2;                  // even voxel index

    int x = p & (W_ - 1);
    int y = (p >> 7) & (H_ - 1);
    int z = p >> 14;

    const float* fb = flow + (size_t)b * 3 * N_;
    float2 fx2 = __ldcs(reinterpret_cast<const float2*>(fb + p));
    float2 fy2 = __ldcs(reinterpret_cast<const float2*>(fb + N_ + p));
    float2 fz2 = __ldcs(reinterpret_cast<const float2*>(fb + 2 * N_ + p));

    Coord ca = setup(x,     y, z, fx2.x, fy2.x, fz2.x);
    Coord cb = setup(x + 1, y, z, fx2.y, fy2.y, fz2.y);

    const uint2* img = g_py + (size_t)b * N_;

    float2 af0 = face_fetch_lerp(img, ca.i0, ca.ty, ca.tx);
    float2 af1 = face_fetch_lerp(img, ca.i1, ca.ty, ca.tx);
    float2 bf0 = face_fetch_lerp(img, cb.i0, cb.ty, cb.tx);
    float2 bf1 = face_fetch_lerp(img, cb.i1, cb.ty, cb.tx);

    float aoutx = fmaf(ca.tz, af1.x - af0.x, af0.x);
    float aouty = fmaf(ca.tz, af1.y - af0.y, af0.y);
    float boutx = fmaf(cb.tz, bf1.x - bf0.x, bf0.x);
    float bouty = fmaf(cb.tz, bf1.y - bf0.y, bf0.y);

    float* o0 = out + ((size_t)b * C_ + 0) * N_ + p;
    float* o1 = out + ((size_t)b * C_ + 1) * N_ + p;
    __stcs(reinterpret_cast<float2*>(o0), make_float2(aoutx, boutx));
    __stcs(reinterpret_cast<float2*>(o1), make_float2(aouty, bouty));
}

extern "C" void kernel_launch(void* const* d_in, const int* in_sizes, int n_in,
                              void* d_out, int out_size)
{
    const float* image = (const float*)d_in[0];
    const float* flow  = (const float*)d_in[1];
    float* out = (float*)d_out;

    {
        constexpr int total = B_ * N_ / 4;
        interleave_kernel<<<total / 256, 256>>>(image);
    }
    {
        constexpr int total = B_ * N_ / 2;
        warp3d_kernel<<<total / 256, 256>>>(flow, out);
    }
}